// round 2
// baseline (speedup 1.0000x reference)
#include <cuda_runtime.h>

#define BB   256
#define TT   2048
#define INW  29
#define HH   64
#define GG   192   // 3*H
#define OUTW 11

// Scratch (no cudaMalloc allowed): gx gate pre-activations for current layer,
// layer-0 bidirectional output sequence, and final hidden states of layer 1.
__device__ float g_gx[(size_t)2 * BB * TT * GG];       // [dir][b][t][g]  (805 MB)
__device__ float g_out0[(size_t)BB * TT * 2 * HH];      // [b][t][128]     (268 MB)
__device__ float g_hT[2 * BB * HH];                     // [dir][b][h]

typedef unsigned long long u64;

__device__ __forceinline__ u64 pk2(float lo, float hi) {
    u64 r; asm("mov.b64 %0,{%1,%2};" : "=l"(r) : "f"(lo), "f"(hi)); return r;
}
__device__ __forceinline__ void upk2(u64 v, float& lo, float& hi) {
    asm("mov.b64 {%0,%1},%2;" : "=f"(lo), "=f"(hi) : "l"(v));
}
// Packed fp32x2 FMA (Blackwell FFMA2) — 2x FFMA throughput vs 3-reg FFMA.
__device__ __forceinline__ u64 fma2(u64 a, u64 b, u64 c) {
    u64 d; asm("fma.rn.f32x2 %0,%1,%2,%3;" : "=l"(d) : "l"(a), "l"(b), "l"(c)); return d;
}
__device__ __forceinline__ u64 add2(u64 a, u64 b) {
    u64 d; asm("add.rn.f32x2 %0,%1,%2;" : "=l"(d) : "l"(a), "l"(b)); return d;
}

__device__ __forceinline__ float sigm(float x)  { return __fdividef(1.f, 1.f + __expf(-x)); }
__device__ __forceinline__ float tanh_(float x) { return __fdividef(2.f, 1.f + __expf(-2.f * x)) - 1.f; }

// ---------------------------------------------------------------------------
// Layer-0 input GEMM: gx[dir][b][t][g] = bih[g] + sum_k Wih[g][k] * x[b][tin][k]
// tin time-reversed for dir=1 so the recurrence always scans t ascending.
// Block: (t-chunk of 32, b, dir), 192 threads; thread j = gate row j, f32x2
// packs two adjacent timesteps.
// ---------------------------------------------------------------------------
__global__ __launch_bounds__(192) void gx0_kernel(
    const float* __restrict__ x,
    const float* __restrict__ Wf, const float* __restrict__ bf,
    const float* __restrict__ Wb, const float* __restrict__ bb)
{
    int dir = blockIdx.z, b = blockIdx.y, t0 = blockIdx.x * 32;
    const float* W  = dir ? Wb : Wf;
    const float* bi = dir ? bb : bf;
    int j = threadIdx.x;

    u64 w2[INW];
#pragma unroll
    for (int k = 0; k < INW; k++) { float w = W[j * INW + k]; w2[k] = pk2(w, w); }
    float bias = bi[j];

    __shared__ float2 xs[INW][16];   // [k][t-pair]
    for (int idx = j; idx < 32 * INW; idx += 192) {
        int tt = idx / INW, k = idx - tt * INW;
        int t = t0 + tt, tin = dir ? (TT - 1 - t) : t;
        float v = x[((size_t)b * TT + tin) * INW + k];
        ((float*)&xs[k][tt >> 1])[tt & 1] = v;
    }
    __syncthreads();

    const u64* xsu = (const u64*)xs;
    float* gxp = g_gx + ((size_t)(dir * BB + b) * TT + t0) * GG;
#pragma unroll 2
    for (int p = 0; p < 16; p++) {
        u64 acc = pk2(bias, bias);
#pragma unroll
        for (int k = 0; k < INW; k++) acc = fma2(w2[k], xsu[k * 16 + p], acc);
        float lo, hi; upk2(acc, lo, hi);
        gxp[(2 * p)     * GG + j] = lo;
        gxp[(2 * p + 1) * GG + j] = hi;
    }
}

// ---------------------------------------------------------------------------
// Layer-1 input GEMM (K=128): K split across 2 thread halves, packed weights
// in registers, partial sums combined through shared memory.
// Block: (t-chunk of 32, b, dir), 384 threads = (gate j in [0,192)) x (kh in {0,1}).
// ---------------------------------------------------------------------------
__global__ __launch_bounds__(384, 1) void gx1_kernel(
    const float* __restrict__ Wf, const float* __restrict__ bf,
    const float* __restrict__ Wb, const float* __restrict__ bb)
{
    int dir = blockIdx.z, b = blockIdx.y, t0 = blockIdx.x * 32;
    const float* W  = dir ? Wb : Wf;
    const float* bi = dir ? bb : bf;
    int tid = threadIdx.x;
    int kh = tid / 192;          // warp-uniform (warps 0-5 -> 0, 6-11 -> 1)
    int j  = tid - kh * 192;

    u64 w2[HH];
#pragma unroll
    for (int k = 0; k < HH; k++) { float w = W[j * (2 * HH) + kh * HH + k]; w2[k] = pk2(w, w); }
    float bias = bi[j];

    __shared__ float2 ins[2 * HH][16];   // [k][t-pair], 16 KB
    __shared__ float2 ps[2][GG][2];      // partial sums [p-slot][gate][kh]

    for (int idx = tid; idx < 32 * 2 * HH; idx += 384) {
        int t_ = idx >> 7, k = idx & 127;
        int t = t0 + t_, tin = dir ? (TT - 1 - t) : t;
        float v = g_out0[((size_t)b * TT + tin) * (2 * HH) + k];
        ((float*)&ins[k][t_ >> 1])[t_ & 1] = v;
    }
    __syncthreads();

    const u64* insu = (const u64*)ins;
    float* gxp = g_gx + ((size_t)(dir * BB + b) * TT + t0) * GG;
    for (int p = 0; p < 16; p += 2) {
        u64 a0 = pk2(0.f, 0.f), a1 = pk2(0.f, 0.f);
#pragma unroll
        for (int k = 0; k < HH; k++) {
            a0 = fma2(w2[k], insu[(kh * HH + k) * 16 + p],     a0);
            a1 = fma2(w2[k], insu[(kh * HH + k) * 16 + p + 1], a1);
        }
        *(u64*)&ps[0][j][kh] = a0;
        *(u64*)&ps[1][j][kh] = a1;
        __syncthreads();
        if (kh == 0) {
            float2 q0a = ps[0][j][0], q0b = ps[0][j][1];
            float2 q1a = ps[1][j][0], q1b = ps[1][j][1];
            gxp[(2 * p)     * GG + j] = q0a.x + q0b.x + bias;
            gxp[(2 * p + 1) * GG + j] = q0a.y + q0b.y + bias;
            gxp[(2 * p + 2) * GG + j] = q1a.x + q1b.x + bias;
            gxp[(2 * p + 3) * GG + j] = q1a.y + q1b.y + bias;
        }
        __syncthreads();
    }
}

// ---------------------------------------------------------------------------
// GRU recurrence: one CTA per (dir, batch-pair). 192 threads: thread j owns
// gate row j with the Whh row duplicated-packed in registers; the two batches
// of the pair ride the two f32x2 lanes. gx is prefetched 2 steps ahead.
// layer==0 writes the bidirectional sequence to g_out0; layer==1 writes g_hT.
// ---------------------------------------------------------------------------
__global__ __launch_bounds__(192, 2) void recur_kernel(
    const float* __restrict__ Whf, const float* __restrict__ bhf,
    const float* __restrict__ Whb, const float* __restrict__ bhb,
    int layer)
{
    int pair = blockIdx.x, dir = blockIdx.y;
    int b0 = 2 * pair, b1 = b0 + 1;
    const float* W  = dir ? Whb : Whf;
    const float* bh = dir ? bhb : bhf;
    int j = threadIdx.x;

    u64 ww[HH];
#pragma unroll
    for (int k = 0; k < HH; k++) { float w = W[j * HH + k]; ww[k] = pk2(w, w); }
    float bj = bh[j];

    __shared__ float2 h2[HH];     // hidden state, lanes = (b0, b1)
    __shared__ float2 s2[GG];     // gate pre-activations (r,z: x+h summed; n: h only)
    __shared__ float2 gn2[HH];    // gx n-part
    if (j < HH) h2[j] = make_float2(0.f, 0.f);

    const float* gx0p = g_gx + ((size_t)(dir * BB + b0) * TT) * GG + j;
    const float* gx1p = g_gx + ((size_t)(dir * BB + b1) * TT) * GG + j;
    float ga0 = gx0p[0],  ga1 = gx1p[0];
    float gb0 = gx0p[GG], gb1 = gx1p[GG];
    __syncthreads();

    const u64* h2u = (const u64*)h2;
    for (int t = 0; t < TT; t++) {
        float gc0 = 0.f, gc1 = 0.f;
        if (t + 2 < TT) { gc0 = gx0p[(size_t)(t + 2) * GG]; gc1 = gx1p[(size_t)(t + 2) * GG]; }

        u64 acc = pk2(bj, bj), accB = pk2(0.f, 0.f);
#pragma unroll
        for (int k = 0; k < HH; k += 2) {
            acc  = fma2(ww[k],     h2u[k],     acc);
            accB = fma2(ww[k + 1], h2u[k + 1], accB);
        }
        u64 s = add2(acc, accB);
        u64 g = pk2(ga0, ga1);
        if (j < 2 * HH) { *(u64*)&s2[j] = add2(s, g); }
        else            { *(u64*)&s2[j] = s; *(u64*)&gn2[j - 2 * HH] = g; }
        __syncthreads();

        if (j < HH) {
            float2 sr = s2[j], sz = s2[HH + j], hn = s2[2 * HH + j];
            float2 xn = gn2[j], hp = h2[j];
            float r0 = sigm(sr.x), r1 = sigm(sr.y);
            float z0 = sigm(sz.x), z1 = sigm(sz.y);
            float n0 = tanh_(fmaf(r0, hn.x, xn.x));
            float n1 = tanh_(fmaf(r1, hn.y, xn.y));
            float hN0 = fmaf(z0, hp.x - n0, n0);   // (1-z)n + z h
            float hN1 = fmaf(z1, hp.y - n1, n1);
            h2[j] = make_float2(hN0, hN1);
            if (layer == 0) {
                int tout = dir ? (TT - 1 - t) : t;
                g_out0[((size_t)b0 * TT + tout) * (2 * HH) + dir * HH + j] = hN0;
                g_out0[((size_t)b1 * TT + tout) * (2 * HH) + dir * HH + j] = hN1;
            }
        }
        __syncthreads();
        ga0 = gb0; ga1 = gb1; gb0 = gc0; gb1 = gc1;
    }

    if (layer == 1 && j < HH) {
        g_hT[(dir * BB + b0) * HH + j] = h2[j].x;
        g_hT[(dir * BB + b1) * HH + j] = h2[j].y;
    }
}

// ---------------------------------------------------------------------------
// Head: LayerNorm(concat(hTf, hTb)) -> ReLU(W1) -> W2. One block per batch.
// ---------------------------------------------------------------------------
__global__ __launch_bounds__(128) void head_kernel(
    const float* __restrict__ ln_g, const float* __restrict__ ln_b,
    const float* __restrict__ W1,  const float* __restrict__ b1,
    const float* __restrict__ W2,  const float* __restrict__ b2,
    float* __restrict__ out)
{
    int b = blockIdx.x, i = threadIdx.x;
    __shared__ float y[128];
    __shared__ float hh[64];
    __shared__ float red[16];

    float e = (i < 64) ? g_hT[(0 * BB + b) * HH + i]
                       : g_hT[(1 * BB + b) * HH + (i - 64)];
    float s = e, q = e * e;
#pragma unroll
    for (int o = 16; o > 0; o >>= 1) {
        s += __shfl_down_sync(0xffffffffu, s, o);
        q += __shfl_down_sync(0xffffffffu, q, o);
    }
    int w = i >> 5, lane = i & 31;
    if (lane == 0) { red[w] = s; red[8 + w] = q; }
    __syncthreads();
    float mu  = (red[0] + red[1] + red[2] + red[3]) * (1.f / 128.f);
    float ms  = (red[8] + red[9] + red[10] + red[11]) * (1.f / 128.f);
    float var = ms - mu * mu;
    float inv = rsqrtf(var + 1e-5f);
    y[i] = (e - mu) * inv * ln_g[i] + ln_b[i];
    __syncthreads();

    if (i < 64) {
        float a = b1[i];
#pragma unroll 4
        for (int k = 0; k < 128; k++) a = fmaf(W1[i * 128 + k], y[k], a);
        hh[i] = fmaxf(a, 0.f);
    }
    __syncthreads();
    if (i < OUTW) {
        float a = b2[i];
#pragma unroll
        for (int k = 0; k < 64; k++) a = fmaf(W2[i * 64 + k], hh[k], a);
        out[b * OUTW + i] = a;
    }
}

extern "C" void kernel_launch(void* const* d_in, const int* in_sizes, int n_in,
                              void* d_out, int out_size)
{
    const float* x     = (const float*)d_in[0];
    const float* Wih00 = (const float*)d_in[1];
    const float* Whh00 = (const float*)d_in[2];
    const float* bih00 = (const float*)d_in[3];
    const float* bhh00 = (const float*)d_in[4];
    const float* Wih01 = (const float*)d_in[5];
    const float* Whh01 = (const float*)d_in[6];
    const float* bih01 = (const float*)d_in[7];
    const float* bhh01 = (const float*)d_in[8];
    const float* Wih10 = (const float*)d_in[9];
    const float* Whh10 = (const float*)d_in[10];
    const float* bih10 = (const float*)d_in[11];
    const float* bhh10 = (const float*)d_in[12];
    const float* Wih11 = (const float*)d_in[13];
    const float* Whh11 = (const float*)d_in[14];
    const float* bih11 = (const float*)d_in[15];
    const float* bhh11 = (const float*)d_in[16];
    const float* ln_g  = (const float*)d_in[17];
    const float* ln_b  = (const float*)d_in[18];
    const float* W1    = (const float*)d_in[19];
    const float* b1    = (const float*)d_in[20];
    const float* W2    = (const float*)d_in[21];
    const float* b2    = (const float*)d_in[22];

    gx0_kernel<<<dim3(TT / 32, BB, 2), 192>>>(x, Wih00, bih00, Wih01, bih01);
    recur_kernel<<<dim3(BB / 2, 2), 192>>>(Whh00, bhh00, Whh01, bhh01, 0);
    gx1_kernel<<<dim3(TT / 32, BB, 2), 384>>>(Wih10, bih10, Wih11, bih11);
    recur_kernel<<<dim3(BB / 2, 2), 192>>>(Whh10, bhh10, Whh11, bhh11, 1);
    head_kernel<<<BB, 128>>>(ln_g, ln_b, W1, b1, W2, b2, (float*)d_out);
}

// round 3
// speedup vs baseline: 1.4188x; 1.4188x over previous
#include <cuda_runtime.h>

#define BB   256
#define TT   2048
#define INW  29
#define HH   64
#define GG   192   // 3*H
#define OUTW 11

// Scratch (no cudaMalloc allowed).
__device__ float g_gx[(size_t)2 * BB * TT * GG];       // [dir][b][t][g] (natural t)
__device__ float g_out0[(size_t)BB * TT * 2 * HH];      // [b][t][128]
__device__ float g_hT[2 * BB * HH];                     // [dir][b][h]

typedef unsigned long long u64;

__device__ __forceinline__ u64 pk2(float lo, float hi) {
    u64 r; asm("mov.b64 %0,{%1,%2};" : "=l"(r) : "f"(lo), "f"(hi)); return r;
}
__device__ __forceinline__ void upk2(u64 v, float& lo, float& hi) {
    asm("mov.b64 {%0,%1},%2;" : "=f"(lo), "=f"(hi) : "l"(v));
}
// Packed fp32x2 FMA (Blackwell FFMA2) — 2x FFMA throughput vs 3-reg FFMA.
__device__ __forceinline__ u64 fma2(u64 a, u64 b, u64 c) {
    u64 d; asm("fma.rn.f32x2 %0,%1,%2,%3;" : "=l"(d) : "l"(a), "l"(b), "l"(c)); return d;
}
__device__ __forceinline__ u64 add2(u64 a, u64 b) {
    u64 d; asm("add.rn.f32x2 %0,%1,%2;" : "=l"(d) : "l"(a), "l"(b)); return d;
}
__device__ __forceinline__ float hadd2(u64 v) {
    float lo, hi; upk2(v, lo, hi); return lo + hi;
}

__device__ __forceinline__ float sigm(float x)  { return __fdividef(1.f, 1.f + __expf(-x)); }
__device__ __forceinline__ float tanh_(float x) { return __fdividef(2.f, 1.f + __expf(-2.f * x)) - 1.f; }

// ---------------------------------------------------------------------------
// Layer-0 input GEMM: gx[dir][b][t][g] = bih[g] + sum_k Wih[g][k]*x[b][t][k]
// Natural time order for both dirs (recurrence walks backward for dir=1).
// Block: 64 timesteps x one (b, dir). 192 threads, thread j = gate row.
// f32x2 lanes = 2 adjacent timesteps; LDS.128 feeds 4 timesteps per load.
// ---------------------------------------------------------------------------
__global__ __launch_bounds__(192) void gx0_kernel(
    const float* __restrict__ x,
    const float* __restrict__ Wf, const float* __restrict__ bf,
    const float* __restrict__ Wb, const float* __restrict__ bb)
{
    int dir = blockIdx.z, b = blockIdx.y, t0 = blockIdx.x * 64;
    const float* W  = dir ? Wb : Wf;
    const float* bi = dir ? bb : bf;
    int j = threadIdx.x;

    u64 w2[INW];
#pragma unroll
    for (int k = 0; k < INW; k++) { float w = W[j * INW + k]; w2[k] = pk2(w, w); }
    float bias = bi[j];

    __shared__ __align__(16) float2 xs[INW][32];   // [k][t-pair], 64 timesteps
    for (int idx = j; idx < 64 * INW; idx += 192) {
        int tt = idx / INW, k = idx - tt * INW;
        float v = x[((size_t)b * TT + t0 + tt) * INW + k];
        ((float*)&xs[k][tt >> 1])[tt & 1] = v;
    }
    __syncthreads();

    const ulonglong2* xsq = (const ulonglong2*)xs;  // [k][16] pairs-of-pairs
    float* gxp = g_gx + ((size_t)(dir * BB + b) * TT + t0) * GG + j;
#pragma unroll 1
    for (int p2 = 0; p2 < 16; p2++) {
        u64 a0 = 0ull, a1 = 0ull;
#pragma unroll
        for (int k = 0; k < INW; k++) {
            ulonglong2 v = xsq[k * 16 + p2];
            a0 = fma2(w2[k], v.x, a0);
            a1 = fma2(w2[k], v.y, a1);
        }
        float q0, q1, q2, q3;
        upk2(a0, q0, q1); upk2(a1, q2, q3);
        gxp[(size_t)(4 * p2)     * GG] = q0 + bias;
        gxp[(size_t)(4 * p2 + 1) * GG] = q1 + bias;
        gxp[(size_t)(4 * p2 + 2) * GG] = q2 + bias;
        gxp[(size_t)(4 * p2 + 3) * GG] = q3 + bias;
    }
}

// ---------------------------------------------------------------------------
// Layer-1 input GEMM (K=128). K split across lane halves of the same warp:
// warp w covers 16 gate rows; lanes l and l^16 hold the two K-halves of gate
// j = w*16 + (l&15). Combine with one shfl_xor — no barriers in the loop.
// Pairwise-k f32x2 packing (weights packed once, not duplicated).
// Block: 64 timesteps x one (b, dir). 384 threads = 12 warps.
// ---------------------------------------------------------------------------
__global__ __launch_bounds__(384) void gx1_kernel(
    const float* __restrict__ Wf, const float* __restrict__ bf,
    const float* __restrict__ Wb, const float* __restrict__ bb)
{
    int dir = blockIdx.z, b = blockIdx.y, t0 = blockIdx.x * 64;
    const float* W  = dir ? Wb : Wf;
    const float* bi = dir ? bb : bf;
    int tid = threadIdx.x;
    int w = tid >> 5, l = tid & 31;
    int j  = (w << 4) | (l & 15);
    int kh = l >> 4;

    u64 w2[32];                      // pairwise-k packed K-half
#pragma unroll
    for (int i = 0; i < 32; i++)
        w2[i] = pk2(W[j * 128 + kh * 64 + 2 * i], W[j * 128 + kh * 64 + 2 * i + 1]);
    float bias = bi[j];

    __shared__ __align__(16) float ins[64][128];   // [t][k], 32 KB
    {
        const float4* src = (const float4*)(g_out0 + ((size_t)b * TT + t0) * 128);
        float4* dst = (float4*)ins;
        for (int idx = tid; idx < 64 * 32; idx += 384) dst[idx] = src[idx];
    }
    __syncthreads();

    float* gxp = g_gx + ((size_t)(dir * BB + b) * TT + t0) * GG + j;
#pragma unroll 1
    for (int t = 0; t < 64; t++) {
        const ulonglong2* row = (const ulonglong2*)&ins[t][kh * 64];
        u64 a0 = 0ull, a1 = 0ull;
#pragma unroll
        for (int i = 0; i < 16; i++) {
            ulonglong2 v = row[i];
            a0 = fma2(w2[2 * i],     v.x, a0);
            a1 = fma2(w2[2 * i + 1], v.y, a1);
        }
        float s = hadd2(add2(a0, a1));
        s += __shfl_xor_sync(0xffffffffu, s, 16);
        if (kh == 0) gxp[(size_t)t * GG] = s + bias;
    }
}

// ---------------------------------------------------------------------------
// GRU recurrence: one CTA per (dir, batch-pair), 192 threads, 2 CTAs/SM.
// Thread j owns gate row j; weights pairwise-k packed (64 regs). h kept as
// plain float[64] per batch in smem, read via LDS.128 (4 h per load, half the
// shared-pipe traffic of the LDS.64 version). gx read natural-order (forward)
// or reversed (backward), prefetched 2 steps ahead.
// ---------------------------------------------------------------------------
__global__ __launch_bounds__(192, 2) void recur_kernel(
    const float* __restrict__ Whf, const float* __restrict__ bhf,
    const float* __restrict__ Whb, const float* __restrict__ bhb,
    int layer)
{
    int pair = blockIdx.x, dir = blockIdx.y;
    int b0 = 2 * pair, b1 = b0 + 1;
    const float* W  = dir ? Whb : Whf;
    const float* bh = dir ? bhb : bhf;
    int j = threadIdx.x;

    u64 w2[32];                      // (W[j][2i], W[j][2i+1])
#pragma unroll
    for (int i = 0; i < 32; i++) w2[i] = pk2(W[j * HH + 2 * i], W[j * HH + 2 * i + 1]);
    float bj = bh[j];

    __shared__ __align__(16) float hA[HH];   // h for batch b0
    __shared__ __align__(16) float hB[HH];   // h for batch b1
    __shared__ float2 s2[GG];                // gate pre-acts, lanes=(b0,b1)
    __shared__ float2 gn2[HH];               // gx n-part
    if (j < HH) { hA[j] = 0.f; hB[j] = 0.f; }

    long stp = dir ? -(long)GG : (long)GG;
    const float* pA = g_gx + ((size_t)(dir * BB + b0) * TT + (dir ? TT - 1 : 0)) * GG + j;
    const float* pB = pA + (size_t)TT * GG;
    float cur0 = pA[0],   cur1 = pB[0];
    float nxt0 = pA[stp], nxt1 = pB[stp];
    __syncthreads();

    const ulonglong2* hAq = (const ulonglong2*)hA;
    const ulonglong2* hBq = (const ulonglong2*)hB;

    for (int t = 0; t < TT; t++) {
        float f0 = 0.f, f1 = 0.f;
        if (t + 2 < TT) { f0 = pA[2 * stp]; f1 = pB[2 * stp]; }
        pA += stp; pB += stp;

        u64 aA0 = 0ull, aA1 = 0ull, aB0 = 0ull, aB1 = 0ull;
#pragma unroll
        for (int i = 0; i < 16; i++) {
            ulonglong2 va = hAq[i];
            ulonglong2 vb = hBq[i];
            aA0 = fma2(w2[2 * i],     va.x, aA0);
            aA1 = fma2(w2[2 * i + 1], va.y, aA1);
            aB0 = fma2(w2[2 * i],     vb.x, aB0);
            aB1 = fma2(w2[2 * i + 1], vb.y, aB1);
        }
        float sA = hadd2(add2(aA0, aA1)) + bj;
        float sB = hadd2(add2(aB0, aB1)) + bj;

        if (j < 2 * HH) {
            s2[j] = make_float2(sA + cur0, sB + cur1);      // r,z: x-part folded in
        } else {
            s2[j] = make_float2(sA, sB);                    // n: h-part only
            gn2[j - 2 * HH] = make_float2(cur0, cur1);      // n: x-part separate
        }
        __syncthreads();

        if (j < HH) {
            float2 sr = s2[j], sz = s2[HH + j], hn = s2[2 * HH + j];
            float2 xn = gn2[j];
            float hp0 = hA[j], hp1 = hB[j];
            float r0 = sigm(sr.x), r1 = sigm(sr.y);
            float z0 = sigm(sz.x), z1 = sigm(sz.y);
            float n0 = tanh_(fmaf(r0, hn.x, xn.x));
            float n1 = tanh_(fmaf(r1, hn.y, xn.y));
            float hN0 = fmaf(z0, hp0 - n0, n0);   // (1-z)n + z h
            float hN1 = fmaf(z1, hp1 - n1, n1);
            hA[j] = hN0; hB[j] = hN1;
            if (layer == 0) {
                int tout = dir ? (TT - 1 - t) : t;
                g_out0[((size_t)b0 * TT + tout) * (2 * HH) + dir * HH + j] = hN0;
                g_out0[((size_t)b1 * TT + tout) * (2 * HH) + dir * HH + j] = hN1;
            }
        }
        __syncthreads();
        cur0 = nxt0; cur1 = nxt1; nxt0 = f0; nxt1 = f1;
    }

    if (layer == 1 && j < HH) {
        g_hT[(dir * BB + b0) * HH + j] = hA[j];
        g_hT[(dir * BB + b1) * HH + j] = hB[j];
    }
}

// ---------------------------------------------------------------------------
// Head: LayerNorm(concat(hTf, hTb)) -> ReLU(W1) -> W2. One block per batch.
// ---------------------------------------------------------------------------
__global__ __launch_bounds__(128) void head_kernel(
    const float* __restrict__ ln_g, const float* __restrict__ ln_b,
    const float* __restrict__ W1,  const float* __restrict__ b1,
    const float* __restrict__ W2,  const float* __restrict__ b2,
    float* __restrict__ out)
{
    int b = blockIdx.x, i = threadIdx.x;
    __shared__ float y[128];
    __shared__ float hh[64];
    __shared__ float red[16];

    float e = (i < 64) ? g_hT[(0 * BB + b) * HH + i]
                       : g_hT[(1 * BB + b) * HH + (i - 64)];
    float s = e, q = e * e;
#pragma unroll
    for (int o = 16; o > 0; o >>= 1) {
        s += __shfl_down_sync(0xffffffffu, s, o);
        q += __shfl_down_sync(0xffffffffu, q, o);
    }
    int w = i >> 5, lane = i & 31;
    if (lane == 0) { red[w] = s; red[8 + w] = q; }
    __syncthreads();
    float mu  = (red[0] + red[1] + red[2] + red[3]) * (1.f / 128.f);
    float ms  = (red[8] + red[9] + red[10] + red[11]) * (1.f / 128.f);
    float var = ms - mu * mu;
    float inv = rsqrtf(var + 1e-5f);
    y[i] = (e - mu) * inv * ln_g[i] + ln_b[i];
    __syncthreads();

    if (i < 64) {
        float a = b1[i];
#pragma unroll 4
        for (int k = 0; k < 128; k++) a = fmaf(W1[i * 128 + k], y[k], a);
        hh[i] = fmaxf(a, 0.f);
    }
    __syncthreads();
    if (i < OUTW) {
        float a = b2[i];
#pragma unroll
        for (int k = 0; k < 64; k++) a = fmaf(W2[i * 64 + k], hh[k], a);
        out[b * OUTW + i] = a;
    }
}

extern "C" void kernel_launch(void* const* d_in, const int* in_sizes, int n_in,
                              void* d_out, int out_size)
{
    const float* x     = (const float*)d_in[0];
    const float* Wih00 = (const float*)d_in[1];
    const float* Whh00 = (const float*)d_in[2];
    const float* bih00 = (const float*)d_in[3];
    const float* bhh00 = (const float*)d_in[4];
    const float* Wih01 = (const float*)d_in[5];
    const float* Whh01 = (const float*)d_in[6];
    const float* bih01 = (const float*)d_in[7];
    const float* bhh01 = (const float*)d_in[8];
    const float* Wih10 = (const float*)d_in[9];
    const float* Whh10 = (const float*)d_in[10];
    const float* bih10 = (const float*)d_in[11];
    const float* bhh10 = (const float*)d_in[12];
    const float* Wih11 = (const float*)d_in[13];
    const float* Whh11 = (const float*)d_in[14];
    const float* bih11 = (const float*)d_in[15];
    const float* bhh11 = (const float*)d_in[16];
    const float* ln_g  = (const float*)d_in[17];
    const float* ln_b  = (const float*)d_in[18];
    const float* W1    = (const float*)d_in[19];
    const float* b1    = (const float*)d_in[20];
    const float* W2    = (const float*)d_in[21];
    const float* b2    = (const float*)d_in[22];

    gx0_kernel<<<dim3(TT / 64, BB, 2), 192>>>(x, Wih00, bih00, Wih01, bih01);
    recur_kernel<<<dim3(BB / 2, 2), 192>>>(Whh00, bhh00, Whh01, bhh01, 0);
    gx1_kernel<<<dim3(TT / 64, BB, 2), 384>>>(Wih10, bih10, Wih11, bih11);
    recur_kernel<<<dim3(BB / 2, 2), 192>>>(Whh10, bhh10, Whh11, bhh11, 1);
    head_kernel<<<BB, 128>>>(ln_g, ln_b, W1, b1, W2, b2, (float*)d_out);
}